// round 2
// baseline (speedup 1.0000x reference)
#include <cuda_runtime.h>
#include <cstdint>

#define NU_  100000
#define NI_  100000
#define NE_  600000
#define FU_  96
#define FI_  160
#define HH   128
#define OUTD 64
#define LN_EPS 1e-5f

// ---------------- scratch (device globals; no runtime allocation) ----------------
__device__ float g_hu  [NU_ * HH];
__device__ float g_hi  [NI_ * HH];
__device__ float g_aggu[NU_ * HH];
__device__ float g_aggi[NI_ * HH];
__device__ float g_hu1 [NU_ * HH];
__device__ float g_hi1 [NI_ * HH];
__device__ float g_invu[NU_];
__device__ float g_invi[NI_];
__device__ int   g_cntu[NU_];
__device__ int   g_cnti[NI_];

// ---------------- packed f32x2 helpers (sm_103a full-rate FMA path) ----------------
__device__ __forceinline__ unsigned long long pack_dup(float v) {
    unsigned int u = __float_as_uint(v);
    unsigned long long r;
    asm("mov.b64 %0, {%1, %1};" : "=l"(r) : "r"(u));
    return r;
}
__device__ __forceinline__ void fma2(unsigned long long& d, unsigned long long a, unsigned long long b) {
    asm("fma.rn.f32x2 %0, %1, %2, %0;" : "+l"(d) : "l"(a), "l"(b));
}
__device__ __forceinline__ float2 unpack2(unsigned long long v) {
    unsigned int lo, hi;
    asm("mov.b64 {%0, %1}, %2;" : "=r"(lo), "=r"(hi) : "l"(v));
    return make_float2(__uint_as_float(lo), __uint_as_float(hi));
}

// ---------------- utility kernels ----------------
__global__ void zero_all_kernel(int zero_counts) {
    size_t stride = (size_t)gridDim.x * blockDim.x;
    for (size_t i = (size_t)blockIdx.x * blockDim.x + threadIdx.x; i < (size_t)NU_ * HH; i += stride) {
        g_aggu[i] = 0.f;
        g_aggi[i] = 0.f;
    }
    if (zero_counts) {
        for (size_t t = (size_t)blockIdx.x * blockDim.x + threadIdx.x; t < NU_; t += stride) {
            g_cntu[t] = 0;
            g_cnti[t] = 0;
        }
    }
}

__global__ void count_kernel(const int* __restrict__ eui, const int* __restrict__ eiu) {
    int e = blockIdx.x * blockDim.x + threadIdx.x;
    if (e < NE_) {
        atomicAdd(&g_cnti[eui[NE_ + e]], 1);   // edge_ui dst = item
        atomicAdd(&g_cntu[eiu[NE_ + e]], 1);   // edge_iu dst = user
    }
}

__global__ void invdeg_kernel() {
    int i = blockIdx.x * blockDim.x + threadIdx.x;
    if (i < NU_) {
        g_invu[i] = 1.f / (float)max(g_cntu[i], 1);
        g_invi[i] = 1.f / (float)max(g_cnti[i], 1);
    }
}

// one warp handles one edge's 128-float row (each thread: 4 floats)
__global__ void scatter_kernel(const float* __restrict__ feat, const int* __restrict__ edge,
                               float* __restrict__ agg) {
    long long t = (long long)blockIdx.x * blockDim.x + threadIdx.x;
    if (t >= (long long)NE_ * 32) return;
    int e  = (int)(t >> 5);
    int f4 = (int)(t & 31) << 2;
    int s = edge[e];
    int d = edge[NE_ + e];
    const float4 v = *(const float4*)(feat + (size_t)s * HH + f4);
    float* dst = agg + (size_t)d * HH + f4;
    atomicAdd(dst + 0, v.x);
    atomicAdd(dst + 1, v.y);
    atomicAdd(dst + 2, v.z);
    atomicAdd(dst + 3, v.w);
}

// ---------------- input projection: Y = relu(X @ W + b), NOUT = 128 ----------------
template <int K, int TM, int WARPS>
__global__ void proj_kernel(const float* __restrict__ X, const float* __restrict__ W,
                            const float* __restrict__ bias, float* __restrict__ Y) {
    constexpr int R = TM * WARPS;
    __shared__ float sx[R][K];
    int base = blockIdx.x * R;
    int tid = threadIdx.y * 32 + threadIdx.x;
    for (int i = tid; i < R * (K / 4); i += 32 * WARPS) {
        int r = i / (K / 4), c = i % (K / 4);
        ((float4*)sx[r])[c] = ((const float4*)(X + (size_t)(base + r) * K))[c];
    }
    __syncthreads();

    int tx = threadIdx.x;
    int r0 = threadIdx.y * TM;
    unsigned long long acc[TM][2];
    unsigned long long b0 = ((const unsigned long long*)bias)[tx * 2 + 0];
    unsigned long long b1 = ((const unsigned long long*)bias)[tx * 2 + 1];
#pragma unroll
    for (int r = 0; r < TM; r++) { acc[r][0] = b0; acc[r][1] = b1; }

    const ulonglong2* W2 = (const ulonglong2*)W;
#pragma unroll 4
    for (int k = 0; k < K; k++) {
        ulonglong2 w = W2[k * (HH / 4) + tx];
#pragma unroll
        for (int r = 0; r < TM; r++) {
            unsigned long long a = pack_dup(sx[r0 + r][k]);
            fma2(acc[r][0], a, w.x);
            fma2(acc[r][1], a, w.y);
        }
    }
#pragma unroll
    for (int r = 0; r < TM; r++) {
        float2 v0 = unpack2(acc[r][0]), v1 = unpack2(acc[r][1]);
        float4 o = make_float4(fmaxf(v0.x, 0.f), fmaxf(v0.y, 0.f),
                               fmaxf(v1.x, 0.f), fmaxf(v1.y, 0.f));
        ((float4*)(Y + (size_t)(base + r0 + r) * HH))[tx] = o;
    }
}

// ------- SAGE + LayerNorm fused: y = LN((agg*inv) @ Wl + bl + x @ Wr) [relu] -------
template <int NOUT, bool RELU, int TM, int WARPS>
__global__ void sage_kernel(const float* __restrict__ agg, const float* __restrict__ inv,
                            const float* __restrict__ x,
                            const float* __restrict__ Wl, const float* __restrict__ bl,
                            const float* __restrict__ Wr,
                            const float* __restrict__ gam, const float* __restrict__ bet,
                            float* __restrict__ y) {
    constexpr int R = TM * WARPS;
    constexpr int CPT = NOUT / 32;   // cols per thread: 4 or 2
    constexpr int P = CPT / 2;       // packed f32x2 accumulators per row: 2 or 1
    __shared__ float sa[R][HH];
    __shared__ float sx[R][HH];

    int base = blockIdx.x * R;
    int tid = threadIdx.y * 32 + threadIdx.x;
    for (int i = tid; i < R * (HH / 4); i += 32 * WARPS) {
        int r = i / (HH / 4), c = i % (HH / 4);
        float s = inv[base + r];
        float4 va = ((const float4*)(agg + (size_t)(base + r) * HH))[c];
        va.x *= s; va.y *= s; va.z *= s; va.w *= s;
        ((float4*)sa[r])[c] = va;
        ((float4*)sx[r])[c] = ((const float4*)(x + (size_t)(base + r) * HH))[c];
    }
    __syncthreads();

    int tx = threadIdx.x;
    int r0 = threadIdx.y * TM;

    unsigned long long acc[TM][P];
#pragma unroll
    for (int p = 0; p < P; p++) {
        unsigned long long bp = ((const unsigned long long*)bl)[tx * P + p];
#pragma unroll
        for (int r = 0; r < TM; r++) acc[r][p] = bp;
    }

#pragma unroll 4
    for (int k = 0; k < HH; k++) {
        unsigned long long wl[P], wr[P];
        if constexpr (CPT == 4) {
            ulonglong2 wlv = ((const ulonglong2*)Wl)[k * (NOUT / 4) + tx];
            ulonglong2 wrv = ((const ulonglong2*)Wr)[k * (NOUT / 4) + tx];
            wl[0] = wlv.x; wl[1] = wlv.y;
            wr[0] = wrv.x; wr[1] = wrv.y;
        } else {
            wl[0] = ((const unsigned long long*)Wl)[k * (NOUT / 2) + tx];
            wr[0] = ((const unsigned long long*)Wr)[k * (NOUT / 2) + tx];
        }
#pragma unroll
        for (int r = 0; r < TM; r++) {
            unsigned long long a  = pack_dup(sa[r0 + r][k]);
            unsigned long long xx = pack_dup(sx[r0 + r][k]);
#pragma unroll
            for (int p = 0; p < P; p++) {
                fma2(acc[r][p], a,  wl[p]);
                fma2(acc[r][p], xx, wr[p]);
            }
        }
    }

    float go[CPT], bo[CPT];
#pragma unroll
    for (int c = 0; c < CPT; c++) {
        go[c] = gam[tx * CPT + c];
        bo[c] = bet[tx * CPT + c];
    }

#pragma unroll
    for (int r = 0; r < TM; r++) {
        float v[CPT];
#pragma unroll
        for (int p = 0; p < P; p++) {
            float2 t = unpack2(acc[r][p]);
            v[2 * p] = t.x; v[2 * p + 1] = t.y;
        }
        float s = 0.f, s2 = 0.f;
#pragma unroll
        for (int c = 0; c < CPT; c++) { s += v[c]; s2 += v[c] * v[c]; }
#pragma unroll
        for (int off = 16; off > 0; off >>= 1) {
            s  += __shfl_xor_sync(0xffffffffu, s,  off);
            s2 += __shfl_xor_sync(0xffffffffu, s2, off);
        }
        float mean = s / (float)NOUT;
        float var  = s2 / (float)NOUT - mean * mean;
        float rs = rsqrtf(var + LN_EPS);
        float* yr = y + (size_t)(base + r0 + r) * NOUT + tx * CPT;
        float o[CPT];
#pragma unroll
        for (int c = 0; c < CPT; c++) {
            float t = (v[c] - mean) * rs * go[c] + bo[c];
            o[c] = RELU ? fmaxf(t, 0.f) : t;
        }
        if constexpr (CPT == 4)
            *(float4*)yr = make_float4(o[0], o[1], o[2], o[3]);
        else
            *(float2*)yr = make_float2(o[0], o[1]);
    }
}

// ---------------- launcher ----------------
extern "C" void kernel_launch(void* const* d_in, const int* in_sizes, int n_in,
                              void* d_out, int out_size) {
    (void)in_sizes; (void)n_in; (void)out_size;
    const float* x_user = (const float*)d_in[0];
    const float* x_item = (const float*)d_in[1];
    const int*   eui    = (const int*)d_in[2];
    const int*   eiu    = (const int*)d_in[3];
    const float* Wp_u   = (const float*)d_in[4];
    const float* bp_u   = (const float*)d_in[5];
    const float* Wp_i   = (const float*)d_in[6];
    const float* bp_i   = (const float*)d_in[7];
    const float* Wl0_ui = (const float*)d_in[8];
    const float* bl0_ui = (const float*)d_in[9];
    const float* Wr0_ui = (const float*)d_in[10];
    const float* Wl0_iu = (const float*)d_in[11];
    const float* bl0_iu = (const float*)d_in[12];
    const float* Wr0_iu = (const float*)d_in[13];
    const float* g0_u   = (const float*)d_in[14];
    const float* b0_u   = (const float*)d_in[15];
    const float* g0_i   = (const float*)d_in[16];
    const float* b0_i   = (const float*)d_in[17];
    const float* Wl1_ui = (const float*)d_in[18];
    const float* bl1_ui = (const float*)d_in[19];
    const float* Wr1_ui = (const float*)d_in[20];
    const float* Wl1_iu = (const float*)d_in[21];
    const float* bl1_iu = (const float*)d_in[22];
    const float* Wr1_iu = (const float*)d_in[23];
    const float* g1_u   = (const float*)d_in[24];
    const float* b1_u   = (const float*)d_in[25];
    const float* g1_i   = (const float*)d_in[26];
    const float* b1_i   = (const float*)d_in[27];

    float *hu, *hi, *aggu, *aggi, *hu1, *hi1, *invu, *invi;
    cudaGetSymbolAddress((void**)&hu,   g_hu);
    cudaGetSymbolAddress((void**)&hi,   g_hi);
    cudaGetSymbolAddress((void**)&aggu, g_aggu);
    cudaGetSymbolAddress((void**)&aggi, g_aggi);
    cudaGetSymbolAddress((void**)&hu1,  g_hu1);
    cudaGetSymbolAddress((void**)&hi1,  g_hi1);
    cudaGetSymbolAddress((void**)&invu, g_invu);
    cudaGetSymbolAddress((void**)&invi, g_invi);

    float* out = (float*)d_out;

    dim3 blk(32, 8);
    const int ROWS = 32;                       // TM=4 * WARPS=8
    const int grid_u = NU_ / ROWS;             // 3125
    const int grid_i = NI_ / ROWS;             // 3125
    const int scat_blocks = (int)(((long long)NE_ * 32 + 255) / 256);

    // degrees + zero aggregation buffers
    zero_all_kernel<<<2048, 256>>>(1);
    count_kernel<<<(NE_ + 255) / 256, 256>>>(eui, eiu);
    invdeg_kernel<<<(NU_ + 255) / 256, 256>>>();

    // per-type projections + relu
    proj_kernel<FU_, 4, 8><<<grid_u, blk>>>(x_user, Wp_u, bp_u, hu);
    proj_kernel<FI_, 4, 8><<<grid_i, blk>>>(x_item, Wp_i, bp_i, hi);

    // layer 0 aggregation
    scatter_kernel<<<scat_blocks, 256>>>(hu, eui, aggi);
    scatter_kernel<<<scat_blocks, 256>>>(hi, eiu, aggu);

    // layer 0 SAGE + LN + relu
    sage_kernel<128, true, 4, 8><<<grid_i, blk>>>(aggi, invi, hi, Wl0_ui, bl0_ui, Wr0_ui, g0_i, b0_i, hi1);
    sage_kernel<128, true, 4, 8><<<grid_u, blk>>>(aggu, invu, hu, Wl0_iu, bl0_iu, Wr0_iu, g0_u, b0_u, hu1);

    // layer 1 aggregation
    zero_all_kernel<<<2048, 256>>>(0);
    scatter_kernel<<<scat_blocks, 256>>>(hu1, eui, aggi);
    scatter_kernel<<<scat_blocks, 256>>>(hi1, eiu, aggu);

    // layer 1 SAGE + LN (no relu); outputs: [h_u2 | h_i2]
    sage_kernel<OUTD, false, 4, 8><<<grid_u, blk>>>(aggu, invu, hu1, Wl1_iu, bl1_iu, Wr1_iu, g1_u, b1_u, out);
    sage_kernel<OUTD, false, 4, 8><<<grid_i, blk>>>(aggi, invi, hi1, Wl1_ui, bl1_ui, Wr1_ui, g1_i, b1_i, out + (size_t)NU_ * OUTD);
}

// round 8
// speedup vs baseline: 2.2759x; 2.2759x over previous
#include <cuda_runtime.h>
#include <cstdint>

#define NU_  100000
#define NI_  100000
#define NE_  600000
#define FU_  96
#define FI_  160
#define HH   128
#define OUTD 64
#define LN_EPS 1e-5f

// ---------------- scratch (device globals; no runtime allocation) ----------------
__device__ float g_hu  [NU_ * HH];
__device__ float g_hi  [NI_ * HH];
__device__ float g_aggu[NU_ * HH];
__device__ float g_aggi[NI_ * HH];
__device__ float g_hu1 [NU_ * HH];
__device__ float g_hi1 [NI_ * HH];
__device__ float g_invu[NU_];
__device__ float g_invi[NI_];
__device__ int   g_cntu[NU_];
__device__ int   g_cnti[NI_];

// ---------------- utility kernels ----------------
__global__ void zero_all_kernel(int zero_counts) {
    size_t stride = (size_t)gridDim.x * blockDim.x;
    for (size_t i = (size_t)blockIdx.x * blockDim.x + threadIdx.x; i < (size_t)NU_ * HH; i += stride) {
        g_aggu[i] = 0.f;
        g_aggi[i] = 0.f;
    }
    if (zero_counts) {
        for (size_t t = (size_t)blockIdx.x * blockDim.x + threadIdx.x; t < NU_; t += stride) {
            g_cntu[t] = 0;
            g_cnti[t] = 0;
        }
    }
}

__global__ void count_kernel(const int* __restrict__ eui, const int* __restrict__ eiu) {
    int e = blockIdx.x * blockDim.x + threadIdx.x;
    if (e < NE_) {
        atomicAdd(&g_cnti[eui[NE_ + e]], 1);
        atomicAdd(&g_cntu[eiu[NE_ + e]], 1);
    }
}

__global__ void invdeg_kernel() {
    int i = blockIdx.x * blockDim.x + threadIdx.x;
    if (i < NU_) {
        g_invu[i] = 1.f / (float)max(g_cntu[i], 1);
        g_invi[i] = 1.f / (float)max(g_cnti[i], 1);
    }
}

__device__ __forceinline__ void red_add_v4(float* addr, float4 v) {
    asm volatile("red.global.add.v4.f32 [%0], {%1, %2, %3, %4};"
                 :: "l"(addr), "f"(v.x), "f"(v.y), "f"(v.z), "f"(v.w) : "memory");
}

// one warp handles one edge's 128-float row (each thread: one float4 + vector red)
__global__ void scatter_kernel(const float* __restrict__ feat, const int* __restrict__ edge,
                               float* __restrict__ agg) {
    long long t = (long long)blockIdx.x * blockDim.x + threadIdx.x;
    if (t >= (long long)NE_ * 32) return;
    int e  = (int)(t >> 5);
    int f4 = (int)(t & 31) << 2;
    int s = edge[e];
    int d = edge[NE_ + e];
    const float4 v = *(const float4*)(feat + (size_t)s * HH + f4);
    red_add_v4(agg + (size_t)d * HH + f4, v);
}

// ---------------- tf32 mma.sync GEMM (portable PTX, no 'a' features) ----------------
// C[r, n] = sum_k A(r,k) * W(k,n) + bias, A = [A1*inv | A2], W = [W1 ; W2]
// block: 256 threads = 8 warps; each warp: 16 rows x NOUT cols; block: 128 rows.
// K staged in chunks of 32 through smem; warp-level m16n8k8 tf32 mma.
// Epilogue: optional LayerNorm (in-register, 4-lane shfl reduce) + optional ReLU.
template <int KTOT, int K1, int NOUT, bool LN_, bool RELU>
__global__ void __launch_bounds__(256) gemm_mma_kernel(
    const float* __restrict__ A1, const float* __restrict__ inv,
    const float* __restrict__ A2,
    const float* __restrict__ W1, const float* __restrict__ W2,
    const float* __restrict__ bias,
    const float* __restrict__ gam, const float* __restrict__ bet,
    float* __restrict__ y, int nrows)
{
    constexpr int NT = NOUT / 8;      // n-tiles per warp
    constexpr int NC = KTOT / 32;     // K chunks
    constexpr int SA = 36;            // smem A row stride (floats), %32 == 4
    constexpr int SB = NOUT + 8;      // smem B row stride (floats), %32 == 8
    __shared__ float sA[128 * SA];
    __shared__ float sB[32 * SB];
    __shared__ float s_bias[NOUT];
    __shared__ float s_g[NOUT];
    __shared__ float s_be[NOUT];

    int tid  = threadIdx.x;
    int w    = tid >> 5;
    int lane = tid & 31;
    int g    = lane >> 2;   // groupID
    int tig  = lane & 3;    // thread-in-group
    int base = blockIdx.x * 128;

    if (tid < NOUT) {
        s_bias[tid] = bias[tid];
        if (LN_) { s_g[tid] = gam[tid]; s_be[tid] = bet[tid]; }
    }

    float acc[NT][4];
#pragma unroll
    for (int nt = 0; nt < NT; nt++)
#pragma unroll
        for (int q = 0; q < 4; q++) acc[nt][q] = 0.f;

    const uint32_t* sAu = (const uint32_t*)sA;
    const uint32_t* sBu = (const uint32_t*)sB;

    for (int c = 0; c < NC; c++) {
        int k0 = c * 32;
        const float* Asrc;
        const float* Wsrc;
        int rl, ak;
        bool first = (k0 < K1);
        if (first) { Asrc = A1; Wsrc = W1; rl = K1; ak = k0; }
        else       { Asrc = A2; Wsrc = W2; rl = KTOT - K1; ak = k0 - K1; }

        __syncthreads();   // previous chunk's smem reads done

        // stage A chunk: 128 rows x 32 cols
#pragma unroll
        for (int t = 0; t < 4; t++) {
            int slot = tid + t * 256;         // 1024 float4 slots
            int r = slot >> 3, j = slot & 7;
            int gr = base + r;
            float4 v = make_float4(0.f, 0.f, 0.f, 0.f);
            if (gr < nrows) {
                v = *(const float4*)(Asrc + (size_t)gr * rl + ak + j * 4);
                if (inv != nullptr && first) {
                    float sc = inv[gr];
                    v.x *= sc; v.y *= sc; v.z *= sc; v.w *= sc;
                }
            }
            *(float4*)&sA[r * SA + j * 4] = v;
        }
        // stage B chunk: 32 rows x NOUT cols
#pragma unroll
        for (int t = 0; t < NOUT / 32; t++) {
            int slot = tid + t * 256;
            int kr = slot / (NOUT / 4), j = slot % (NOUT / 4);
            float4 v = *(const float4*)(Wsrc + (size_t)(ak + kr) * NOUT + j * 4);
            *(float4*)&sB[kr * SB + j * 4] = v;
        }
        __syncthreads();

#pragma unroll
        for (int kk = 0; kk < 4; kk++) {
            int ar = (w * 16 + g) * SA + kk * 8;
            uint32_t a0 = sAu[ar + tig];
            uint32_t a1 = sAu[ar + 8 * SA + tig];
            uint32_t a2 = sAu[ar + tig + 4];
            uint32_t a3 = sAu[ar + 8 * SA + tig + 4];
#pragma unroll
            for (int nt = 0; nt < NT; nt++) {
                uint32_t b0 = sBu[(kk * 8 + tig) * SB + nt * 8 + g];
                uint32_t b1 = sBu[(kk * 8 + tig + 4) * SB + nt * 8 + g];
                asm volatile(
                    "mma.sync.aligned.m16n8k8.row.col.f32.tf32.tf32.f32 "
                    "{%0,%1,%2,%3}, {%4,%5,%6,%7}, {%8,%9}, {%0,%1,%2,%3};"
                    : "+f"(acc[nt][0]), "+f"(acc[nt][1]), "+f"(acc[nt][2]), "+f"(acc[nt][3])
                    : "r"(a0), "r"(a1), "r"(a2), "r"(a3), "r"(b0), "r"(b1));
            }
        }
    }

    // ---------------- epilogue ----------------
    int r0 = base + w * 16 + g;     // rows g and g+8 of this warp's m16 slab
    int r1 = r0 + 8;

    // add bias
#pragma unroll
    for (int nt = 0; nt < NT; nt++) {
        int cb = nt * 8 + tig * 2;
        float b0f = s_bias[cb], b1f = s_bias[cb + 1];
        acc[nt][0] += b0f; acc[nt][1] += b1f;
        acc[nt][2] += b0f; acc[nt][3] += b1f;
    }

    float mean0 = 0.f, rs0 = 1.f, mean1 = 0.f, rs1 = 1.f;
    if (LN_) {
        float s0 = 0.f, q0 = 0.f, s1 = 0.f, q1 = 0.f;
#pragma unroll
        for (int nt = 0; nt < NT; nt++) {
            s0 += acc[nt][0] + acc[nt][1];
            q0 += acc[nt][0] * acc[nt][0] + acc[nt][1] * acc[nt][1];
            s1 += acc[nt][2] + acc[nt][3];
            q1 += acc[nt][2] * acc[nt][2] + acc[nt][3] * acc[nt][3];
        }
#pragma unroll
        for (int m = 1; m <= 2; m <<= 1) {
            s0 += __shfl_xor_sync(0xffffffffu, s0, m);
            q0 += __shfl_xor_sync(0xffffffffu, q0, m);
            s1 += __shfl_xor_sync(0xffffffffu, s1, m);
            q1 += __shfl_xor_sync(0xffffffffu, q1, m);
        }
        mean0 = s0 / (float)NOUT;
        mean1 = s1 / (float)NOUT;
        float v0 = q0 / (float)NOUT - mean0 * mean0;
        float v1 = q1 / (float)NOUT - mean1 * mean1;
        rs0 = rsqrtf(v0 + LN_EPS);
        rs1 = rsqrtf(v1 + LN_EPS);
    }

    if (r0 < nrows) {
        float* yr = y + (size_t)r0 * NOUT;
#pragma unroll
        for (int nt = 0; nt < NT; nt++) {
            int cb = nt * 8 + tig * 2;
            float o0 = acc[nt][0], o1 = acc[nt][1];
            if (LN_) {
                o0 = (o0 - mean0) * rs0 * s_g[cb]     + s_be[cb];
                o1 = (o1 - mean0) * rs0 * s_g[cb + 1] + s_be[cb + 1];
            }
            if (RELU) { o0 = fmaxf(o0, 0.f); o1 = fmaxf(o1, 0.f); }
            *(float2*)(yr + cb) = make_float2(o0, o1);
        }
    }
    if (r1 < nrows) {
        float* yr = y + (size_t)r1 * NOUT;
#pragma unroll
        for (int nt = 0; nt < NT; nt++) {
            int cb = nt * 8 + tig * 2;
            float o0 = acc[nt][2], o1 = acc[nt][3];
            if (LN_) {
                o0 = (o0 - mean1) * rs1 * s_g[cb]     + s_be[cb];
                o1 = (o1 - mean1) * rs1 * s_g[cb + 1] + s_be[cb + 1];
            }
            if (RELU) { o0 = fmaxf(o0, 0.f); o1 = fmaxf(o1, 0.f); }
            *(float2*)(yr + cb) = make_float2(o0, o1);
        }
    }
}

// ---------------- launcher ----------------
extern "C" void kernel_launch(void* const* d_in, const int* in_sizes, int n_in,
                              void* d_out, int out_size) {
    (void)in_sizes; (void)n_in; (void)out_size;
    const float* x_user = (const float*)d_in[0];
    const float* x_item = (const float*)d_in[1];
    const int*   eui    = (const int*)d_in[2];
    const int*   eiu    = (const int*)d_in[3];
    const float* Wp_u   = (const float*)d_in[4];
    const float* bp_u   = (const float*)d_in[5];
    const float* Wp_i   = (const float*)d_in[6];
    const float* bp_i   = (const float*)d_in[7];
    const float* Wl0_ui = (const float*)d_in[8];
    const float* bl0_ui = (const float*)d_in[9];
    const float* Wr0_ui = (const float*)d_in[10];
    const float* Wl0_iu = (const float*)d_in[11];
    const float* bl0_iu = (const float*)d_in[12];
    const float* Wr0_iu = (const float*)d_in[13];
    const float* g0_u   = (const float*)d_in[14];
    const float* b0_u   = (const float*)d_in[15];
    const float* g0_i   = (const float*)d_in[16];
    const float* b0_i   = (const float*)d_in[17];
    const float* Wl1_ui = (const float*)d_in[18];
    const float* bl1_ui = (const float*)d_in[19];
    const float* Wr1_ui = (const float*)d_in[20];
    const float* Wl1_iu = (const float*)d_in[21];
    const float* bl1_iu = (const float*)d_in[22];
    const float* Wr1_iu = (const float*)d_in[23];
    const float* g1_u   = (const float*)d_in[24];
    const float* b1_u   = (const float*)d_in[25];
    const float* g1_i   = (const float*)d_in[26];
    const float* b1_i   = (const float*)d_in[27];

    float *hu, *hi, *aggu, *aggi, *hu1, *hi1, *invu, *invi;
    cudaGetSymbolAddress((void**)&hu,   g_hu);
    cudaGetSymbolAddress((void**)&hi,   g_hi);
    cudaGetSymbolAddress((void**)&aggu, g_aggu);
    cudaGetSymbolAddress((void**)&aggi, g_aggi);
    cudaGetSymbolAddress((void**)&hu1,  g_hu1);
    cudaGetSymbolAddress((void**)&hi1,  g_hi1);
    cudaGetSymbolAddress((void**)&invu, g_invu);
    cudaGetSymbolAddress((void**)&invi, g_invi);

    float* out = (float*)d_out;

    const int scat_blocks = (int)(((long long)NE_ * 32 + 255) / 256);
    const int gblocks = (NU_ + 127) / 128;   // 782 (NU_ == NI_)

    zero_all_kernel<<<2048, 256>>>(1);
    count_kernel<<<(NE_ + 255) / 256, 256>>>(eui, eiu);
    invdeg_kernel<<<(NU_ + 255) / 256, 256>>>();

    // per-type projections + relu (tf32 mma)
    gemm_mma_kernel<FU_, FU_, HH, false, true><<<gblocks, 256>>>(
        x_user, nullptr, nullptr, Wp_u, nullptr, bp_u, nullptr, nullptr, hu, NU_);
    gemm_mma_kernel<FI_, FI_, HH, false, true><<<gblocks, 256>>>(
        x_item, nullptr, nullptr, Wp_i, nullptr, bp_i, nullptr, nullptr, hi, NI_);

    // layer 0 aggregation
    scatter_kernel<<<scat_blocks, 256>>>(hu, eui, aggi);
    scatter_kernel<<<scat_blocks, 256>>>(hi, eiu, aggu);

    // layer 0 SAGE + LN + relu (K = 128 agg + 128 root)
    gemm_mma_kernel<2 * HH, HH, HH, true, true><<<gblocks, 256>>>(
        aggi, invi, hi, Wl0_ui, Wr0_ui, bl0_ui, g0_i, b0_i, hi1, NI_);
    gemm_mma_kernel<2 * HH, HH, HH, true, true><<<gblocks, 256>>>(
        aggu, invu, hu, Wl0_iu, Wr0_iu, bl0_iu, g0_u, b0_u, hu1, NU_);

    // layer 1 aggregation
    zero_all_kernel<<<2048, 256>>>(0);
    scatter_kernel<<<scat_blocks, 256>>>(hu1, eui, aggi);
    scatter_kernel<<<scat_blocks, 256>>>(hi1, eiu, aggu);

    // layer 1 SAGE + LN (no relu); outputs: [h_u2 | h_i2]
    gemm_mma_kernel<2 * HH, HH, OUTD, true, false><<<gblocks, 256>>>(
        aggu, invu, hu1, Wl1_iu, Wr1_iu, bl1_iu, g1_u, b1_u, out, NU_);
    gemm_mma_kernel<2 * HH, HH, OUTD, true, false><<<gblocks, 256>>>(
        aggi, invi, hi1, Wl1_ui, Wr1_ui, bl1_ui, g1_i, b1_i, out + (size_t)NU_ * OUTD, NI_);
}

// round 11
// speedup vs baseline: 3.7321x; 1.6399x over previous
#include <cuda_runtime.h>
#include <cstdint>

#define NU_  100000
#define NI_  100000
#define NE_  600000
#define FU_  96
#define FI_  160
#define HH   128
#define OUTD 64
#define LN_EPS 1e-5f

// ---------------- scratch (device globals; no runtime allocation) ----------------
__device__ float g_hu  [NU_ * HH];
__device__ float g_hi  [NI_ * HH];
__device__ float g_aggu[NU_ * HH];
__device__ float g_aggi[NI_ * HH];
__device__ float g_hu1 [NU_ * HH];
__device__ float g_hi1 [NI_ * HH];
__device__ int   g_cntu[NU_];
__device__ int   g_cnti[NI_];
__device__ int   g_offu[NU_];
__device__ int   g_offi[NI_];
__device__ int   g_curu[NU_];
__device__ int   g_curi[NI_];
__device__ int   g_bsumu[128];
__device__ int   g_bsumi[128];
__device__ int   g_eidx_ui[NE_];   // src user idx, grouped by dst item
__device__ int   g_eidx_iu[NE_];   // src item idx, grouped by dst user
__device__ float g_wt[131072];     // transposed weights

// ---------------- small helpers ----------------
__device__ __forceinline__ uint32_t smem_u32(const void* p) {
    uint32_t a;
    asm("{ .reg .u64 t; cvta.to.shared.u64 t, %1; cvt.u32.u64 %0, t; }" : "=r"(a) : "l"(p));
    return a;
}

// ---------------- CSR build ----------------
__global__ void zero_cnt_kernel() {
    int i = blockIdx.x * blockDim.x + threadIdx.x;
    if (i < NU_) { g_cntu[i] = 0; g_cnti[i] = 0; }
}

__global__ void count_kernel(const int* __restrict__ eui, const int* __restrict__ eiu) {
    int e = blockIdx.x * blockDim.x + threadIdx.x;
    if (e < NE_) {
        atomicAdd(&g_cnti[eui[NE_ + e]], 1);
        atomicAdd(&g_cntu[eiu[NE_ + e]], 1);
    }
}

// block-level inclusive scan -> exclusive offsets + block totals
__global__ void scan1_kernel(const int* __restrict__ cnt, int* __restrict__ off,
                             int* __restrict__ bsum, int n) {
    __shared__ int s[1024];
    int t = threadIdx.x, i = blockIdx.x * 1024 + t;
    int v = (i < n) ? cnt[i] : 0;
    s[t] = v;
    __syncthreads();
#pragma unroll
    for (int d = 1; d < 1024; d <<= 1) {
        int y = (t >= d) ? s[t - d] : 0;
        __syncthreads();
        s[t] += y;
        __syncthreads();
    }
    if (i < n) off[i] = s[t] - v;
    if (t == 1023) bsum[blockIdx.x] = s[t];
}

__global__ void scan2_kernel(int* __restrict__ bsum, int nb) {
    __shared__ int s[128];
    int t = threadIdx.x;
    int v = (t < nb) ? bsum[t] : 0;
    s[t] = v;
    __syncthreads();
#pragma unroll
    for (int d = 1; d < 128; d <<= 1) {
        int y = (t >= d) ? s[t - d] : 0;
        __syncthreads();
        s[t] += y;
        __syncthreads();
    }
    if (t < nb) bsum[t] = s[t] - v;
}

__global__ void scan3_kernel(int* __restrict__ off, const int* __restrict__ bsum,
                             int* __restrict__ cur, int n) {
    int i = blockIdx.x * 1024 + threadIdx.x;
    if (i < n) {
        int o = off[i] + bsum[blockIdx.x];
        off[i] = o;
        cur[i] = o;
    }
}

__global__ void fill_kernel(const int* __restrict__ eui, const int* __restrict__ eiu) {
    int e = blockIdx.x * blockDim.x + threadIdx.x;
    if (e < NE_) {
        int di = eui[NE_ + e];
        int p  = atomicAdd(&g_curi[di], 1);
        g_eidx_ui[p] = eui[e];
        int du = eiu[NE_ + e];
        int p2 = atomicAdd(&g_curu[du], 1);
        g_eidx_iu[p2] = eiu[e];
    }
}

// ---------------- gather-mean aggregation: warp per destination row ----------------
__global__ void gather_kernel(const float* __restrict__ feat, const int* __restrict__ eidx,
                              const int* __restrict__ off, const int* __restrict__ cnt,
                              float* __restrict__ agg, int n) {
    int gw = (int)(((long long)blockIdx.x * blockDim.x + threadIdx.x) >> 5);
    if (gw >= n) return;
    int lane = threadIdx.x & 31;
    int start = off[gw], c = cnt[gw];
    float4 a0 = make_float4(0.f, 0.f, 0.f, 0.f);
    float4 a1 = make_float4(0.f, 0.f, 0.f, 0.f);
    int j = 0;
    for (; j + 2 <= c; j += 2) {
        int s0 = __ldg(&eidx[start + j]);
        int s1 = __ldg(&eidx[start + j + 1]);
        float4 v0 = *(const float4*)(feat + (size_t)s0 * HH + lane * 4);
        float4 v1 = *(const float4*)(feat + (size_t)s1 * HH + lane * 4);
        a0.x += v0.x; a0.y += v0.y; a0.z += v0.z; a0.w += v0.w;
        a1.x += v1.x; a1.y += v1.y; a1.z += v1.z; a1.w += v1.w;
    }
    if (j < c) {
        int s0 = __ldg(&eidx[start + j]);
        float4 v0 = *(const float4*)(feat + (size_t)s0 * HH + lane * 4);
        a0.x += v0.x; a0.y += v0.y; a0.z += v0.z; a0.w += v0.w;
    }
    float sc = 1.f / (float)max(c, 1);
    float4 r = make_float4((a0.x + a1.x) * sc, (a0.y + a1.y) * sc,
                           (a0.z + a1.z) * sc, (a0.w + a1.w) * sc);
    *(float4*)(agg + (size_t)gw * HH + lane * 4) = r;
}

// ---------------- weight transpose: dst[n][k] = (k<K1 ? W1 : W2)[k][n] ----------------
__global__ void transpose_w_kernel(const float* __restrict__ W1, const float* __restrict__ W2,
                                   float* __restrict__ dst, int K1, int KTOT, int NOUT) {
    int idx = blockIdx.x * blockDim.x + threadIdx.x;
    if (idx >= NOUT * KTOT) return;
    int n = idx / KTOT, k = idx % KTOT;
    float v = (k < K1) ? W1[(size_t)k * NOUT + n] : W2[(size_t)(k - K1) * NOUT + n];
    dst[idx] = v;
}

// ---------------- pipelined tf32 mma GEMM with ldmatrix + cp.async ----------------
// C[r,n] = sum_k A(r,k) * W(k,n) + bias,  A = [A1 | A2] (split at K1), Wt = W^T [NOUT][KTOT]
// block: 256 thr = 8 warps, 128 rows; warp: m16 x NOUT. K chunks of 32 double-buffered.
template <int KTOT, int K1, int NOUT, bool LN_, bool RELU>
__global__ void __launch_bounds__(256) gemm_mma_kernel(
    const float* __restrict__ A1, const float* __restrict__ A2,
    const float* __restrict__ Wt,
    const float* __restrict__ bias,
    const float* __restrict__ gam, const float* __restrict__ bet,
    float* __restrict__ y, int nrows)
{
    constexpr int NT = NOUT / 8;        // n-tiles per warp
    constexpr int NC = KTOT / 32;       // K chunks
    constexpr int ABUF = 128 * 32 * 4;  // bytes per A buffer
    constexpr int BBUF = NOUT * 32 * 4; // bytes per B buffer
    extern __shared__ __align__(128) char smem[];
    float* s_bias = (float*)(smem + 2 * ABUF + 2 * BBUF);
    float* s_g    = s_bias + NOUT;
    float* s_be   = s_g + NOUT;
    uint32_t sb = smem_u32(smem);

    int tid = threadIdx.x;
    int w = tid >> 5, lane = tid & 31;
    int g = lane >> 2, tig = lane & 3;
    int base = blockIdx.x * 128;

    if (tid < NOUT) {
        s_bias[tid] = bias[tid];
        if (LN_) { s_g[tid] = gam[tid]; s_be[tid] = bet[tid]; }
    }

    float acc[NT][4];
#pragma unroll
    for (int nt = 0; nt < NT; nt++)
#pragma unroll
        for (int q = 0; q < 4; q++) acc[nt][q] = 0.f;

    auto stage = [&](int c) {
        uint32_t aB = sb + (c & 1) * ABUF;
        uint32_t bB = sb + 2 * ABUF + (c & 1) * BBUF;
        int k0 = c * 32;
        const float* Asrc; int rl, ak;
        if (k0 < K1) { Asrc = A1; rl = K1; ak = k0; }
        else         { Asrc = A2; rl = KTOT - K1; ak = k0 - K1; }
        // A chunk: 128 rows x 32 floats (1024 x 16B)
#pragma unroll
        for (int t = 0; t < 4; t++) {
            int slot = tid + t * 256;
            int r = slot >> 3, j = slot & 7;
            int gr = base + r;
            const float* src = Asrc + (size_t)gr * rl + ak + j * 4;
            uint32_t dst = aB + r * 128 + ((j ^ (r & 7)) << 4);
            int sz = (gr < nrows) ? 16 : 0;
            asm volatile("cp.async.cg.shared.global [%0], [%1], 16, %2;"
                         :: "r"(dst), "l"(src), "r"(sz));
        }
        // B chunk: NOUT rows x 32 floats
#pragma unroll
        for (int t = 0; t < NOUT / 32; t++) {
            int slot = tid + t * 256;
            int n = slot >> 3, j = slot & 7;
            const float* src = Wt + (size_t)n * KTOT + k0 + j * 4;
            uint32_t dst = bB + n * 128 + ((j ^ (n & 7)) << 4);
            asm volatile("cp.async.cg.shared.global [%0], [%1], 16;"
                         :: "r"(dst), "l"(src));
        }
        asm volatile("cp.async.commit_group;" ::: "memory");
    };

    stage(0);
    for (int c = 0; c < NC; c++) {
        if (c + 1 < NC) {
            stage(c + 1);
            asm volatile("cp.async.wait_group 1;" ::: "memory");
        } else {
            asm volatile("cp.async.wait_group 0;" ::: "memory");
        }
        __syncthreads();
        uint32_t aB = sb + (c & 1) * ABUF;
        uint32_t bB = sb + 2 * ABUF + (c & 1) * BBUF;
#pragma unroll
        for (int kk = 0; kk < 4; kk++) {
            uint32_t a0, a1, a2, a3;
            {
                int m = lane >> 3, i = lane & 7;
                int row = w * 16 + (m & 1) * 8 + i;
                int j = kk * 2 + (m >> 1);
                uint32_t addr = aB + row * 128 + ((j ^ (row & 7)) << 4);
                asm volatile("ldmatrix.sync.aligned.m8n8.x4.shared.b16 {%0,%1,%2,%3}, [%4];"
                             : "=r"(a0), "=r"(a1), "=r"(a2), "=r"(a3) : "r"(addr));
            }
#pragma unroll
            for (int p = 0; p < NT / 2; p++) {
                uint32_t b0, b1, b2, b3;
                {
                    int m = lane >> 3, i = lane & 7;
                    int nrow = p * 16 + (m >> 1) * 8 + i;
                    int j = kk * 2 + (m & 1);
                    uint32_t addr = bB + nrow * 128 + ((j ^ (nrow & 7)) << 4);
                    asm volatile("ldmatrix.sync.aligned.m8n8.x4.shared.b16 {%0,%1,%2,%3}, [%4];"
                                 : "=r"(b0), "=r"(b1), "=r"(b2), "=r"(b3) : "r"(addr));
                }
                asm volatile(
                    "mma.sync.aligned.m16n8k8.row.col.f32.tf32.tf32.f32 "
                    "{%0,%1,%2,%3}, {%4,%5,%6,%7}, {%8,%9}, {%0,%1,%2,%3};"
                    : "+f"(acc[2 * p][0]), "+f"(acc[2 * p][1]), "+f"(acc[2 * p][2]), "+f"(acc[2 * p][3])
                    : "r"(a0), "r"(a1), "r"(a2), "r"(a3), "r"(b0), "r"(b1));
                asm volatile(
                    "mma.sync.aligned.m16n8k8.row.col.f32.tf32.tf32.f32 "
                    "{%0,%1,%2,%3}, {%4,%5,%6,%7}, {%8,%9}, {%0,%1,%2,%3};"
                    : "+f"(acc[2 * p + 1][0]), "+f"(acc[2 * p + 1][1]), "+f"(acc[2 * p + 1][2]), "+f"(acc[2 * p + 1][3])
                    : "r"(a0), "r"(a1), "r"(a2), "r"(a3), "r"(b2), "r"(b3));
            }
        }
        __syncthreads();
    }

    // ---------------- epilogue: bias + optional LN + optional ReLU ----------------
    int r0 = base + w * 16 + g;
    int r1 = r0 + 8;

#pragma unroll
    for (int nt = 0; nt < NT; nt++) {
        int cb = nt * 8 + tig * 2;
        float b0f = s_bias[cb], b1f = s_bias[cb + 1];
        acc[nt][0] += b0f; acc[nt][1] += b1f;
        acc[nt][2] += b0f; acc[nt][3] += b1f;
    }

    float mean0 = 0.f, rs0 = 1.f, mean1 = 0.f, rs1 = 1.f;
    if (LN_) {
        float s0 = 0.f, q0 = 0.f, s1 = 0.f, q1 = 0.f;
#pragma unroll
        for (int nt = 0; nt < NT; nt++) {
            s0 += acc[nt][0] + acc[nt][1];
            q0 += acc[nt][0] * acc[nt][0] + acc[nt][1] * acc[nt][1];
            s1 += acc[nt][2] + acc[nt][3];
            q1 += acc[nt][2] * acc[nt][2] + acc[nt][3] * acc[nt][3];
        }
#pragma unroll
        for (int m = 1; m <= 2; m <<= 1) {
            s0 += __shfl_xor_sync(0xffffffffu, s0, m);
            q0 += __shfl_xor_sync(0xffffffffu, q0, m);
            s1 += __shfl_xor_sync(0xffffffffu, s1, m);
            q1 += __shfl_xor_sync(0xffffffffu, q1, m);
        }
        mean0 = s0 / (float)NOUT;
        mean1 = s1 / (float)NOUT;
        float v0 = q0 / (float)NOUT - mean0 * mean0;
        float v1 = q1 / (float)NOUT - mean1 * mean1;
        rs0 = rsqrtf(v0 + LN_EPS);
        rs1 = rsqrtf(v1 + LN_EPS);
    }

    if (r0 < nrows) {
        float* yr = y + (size_t)r0 * NOUT;
#pragma unroll
        for (int nt = 0; nt < NT; nt++) {
            int cb = nt * 8 + tig * 2;
            float o0 = acc[nt][0], o1 = acc[nt][1];
            if (LN_) {
                o0 = (o0 - mean0) * rs0 * s_g[cb]     + s_be[cb];
                o1 = (o1 - mean0) * rs0 * s_g[cb + 1] + s_be[cb + 1];
            }
            if (RELU) { o0 = fmaxf(o0, 0.f); o1 = fmaxf(o1, 0.f); }
            *(float2*)(yr + cb) = make_float2(o0, o1);
        }
    }
    if (r1 < nrows) {
        float* yr = y + (size_t)r1 * NOUT;
#pragma unroll
        for (int nt = 0; nt < NT; nt++) {
            int cb = nt * 8 + tig * 2;
            float o0 = acc[nt][2], o1 = acc[nt][3];
            if (LN_) {
                o0 = (o0 - mean1) * rs1 * s_g[cb]     + s_be[cb];
                o1 = (o1 - mean1) * rs1 * s_g[cb + 1] + s_be[cb + 1];
            }
            if (RELU) { o0 = fmaxf(o0, 0.f); o1 = fmaxf(o1, 0.f); }
            *(float2*)(yr + cb) = make_float2(o0, o1);
        }
    }
}

// ---------------- launcher ----------------
extern "C" void kernel_launch(void* const* d_in, const int* in_sizes, int n_in,
                              void* d_out, int out_size) {
    (void)in_sizes; (void)n_in; (void)out_size;
    const float* x_user = (const float*)d_in[0];
    const float* x_item = (const float*)d_in[1];
    const int*   eui    = (const int*)d_in[2];
    const int*   eiu    = (const int*)d_in[3];
    const float* Wp_u   = (const float*)d_in[4];
    const float* bp_u   = (const float*)d_in[5];
    const float* Wp_i   = (const float*)d_in[6];
    const float* bp_i   = (const float*)d_in[7];
    const float* Wl0_ui = (const float*)d_in[8];
    const float* bl0_ui = (const float*)d_in[9];
    const float* Wr0_ui = (const float*)d_in[10];
    const float* Wl0_iu = (const float*)d_in[11];
    const float* bl0_iu = (const float*)d_in[12];
    const float* Wr0_iu = (const float*)d_in[13];
    const float* g0_u   = (const float*)d_in[14];
    const float* b0_u   = (const float*)d_in[15];
    const float* g0_i   = (const float*)d_in[16];
    const float* b0_i   = (const float*)d_in[17];
    const float* Wl1_ui = (const float*)d_in[18];
    const float* bl1_ui = (const float*)d_in[19];
    const float* Wr1_ui = (const float*)d_in[20];
    const float* Wl1_iu = (const float*)d_in[21];
    const float* bl1_iu = (const float*)d_in[22];
    const float* Wr1_iu = (const float*)d_in[23];
    const float* g1_u   = (const float*)d_in[24];
    const float* b1_u   = (const float*)d_in[25];
    const float* g1_i   = (const float*)d_in[26];
    const float* b1_i   = (const float*)d_in[27];

    float *hu, *hi, *aggu, *aggi, *hu1, *hi1, *wt;
    int *cntu, *cnti, *offu, *offi, *curu, *curi, *bsumu, *bsumi, *eix_ui, *eix_iu;
    cudaGetSymbolAddress((void**)&hu,   g_hu);
    cudaGetSymbolAddress((void**)&hi,   g_hi);
    cudaGetSymbolAddress((void**)&aggu, g_aggu);
    cudaGetSymbolAddress((void**)&aggi, g_aggi);
    cudaGetSymbolAddress((void**)&hu1,  g_hu1);
    cudaGetSymbolAddress((void**)&hi1,  g_hi1);
    cudaGetSymbolAddress((void**)&wt,   g_wt);
    cudaGetSymbolAddress((void**)&cntu, g_cntu);
    cudaGetSymbolAddress((void**)&cnti, g_cnti);
    cudaGetSymbolAddress((void**)&offu, g_offu);
    cudaGetSymbolAddress((void**)&offi, g_offi);
    cudaGetSymbolAddress((void**)&curu, g_curu);
    cudaGetSymbolAddress((void**)&curi, g_curi);
    cudaGetSymbolAddress((void**)&bsumu, g_bsumu);
    cudaGetSymbolAddress((void**)&bsumi, g_bsumi);
    cudaGetSymbolAddress((void**)&eix_ui, g_eidx_ui);
    cudaGetSymbolAddress((void**)&eix_iu, g_eidx_iu);

    float* out = (float*)d_out;

    // transposed weight regions
    float* wt_pu  = wt;             // 128 x 96
    float* wt_pi  = wt + 12288;     // 128 x 160
    float* wt0_ui = wt + 32768;     // 128 x 256
    float* wt0_iu = wt + 65536;     // 128 x 256
    float* wt1_iu = wt + 98304;     // 64 x 256
    float* wt1_ui = wt + 114688;    // 64 x 256

    const int SM_N128 = 2 * (128 * 32 * 4) + 2 * (128 * 32 * 4) + 3 * 128 * 4;  // 67072
    const int SM_N64  = 2 * (128 * 32 * 4) + 2 * (64 * 32 * 4)  + 3 * 64 * 4;   // 49920
    cudaFuncSetAttribute(gemm_mma_kernel<FU_, FU_, HH, false, true>,
                         cudaFuncAttributeMaxDynamicSharedMemorySize, SM_N128);
    cudaFuncSetAttribute(gemm_mma_kernel<FI_, FI_, HH, false, true>,
                         cudaFuncAttributeMaxDynamicSharedMemorySize, SM_N128);
    cudaFuncSetAttribute(gemm_mma_kernel<2 * HH, HH, HH, true, true>,
                         cudaFuncAttributeMaxDynamicSharedMemorySize, SM_N128);
    cudaFuncSetAttribute(gemm_mma_kernel<2 * HH, HH, OUTD, true, false>,
                         cudaFuncAttributeMaxDynamicSharedMemorySize, SM_N64);

    const int gblocks = (NU_ + 127) / 128;            // 782
    const int sblocks = (NU_ + 1023) / 1024;          // 98
    const int wblocks = (int)(((long long)NU_ * 32 + 255) / 256);  // gather: warp/row

    // CSR build (shared by both layers)
    zero_cnt_kernel<<<(NU_ + 255) / 256, 256>>>();
    count_kernel<<<(NE_ + 255) / 256, 256>>>(eui, eiu);
    scan1_kernel<<<sblocks, 1024>>>(cntu, offu, bsumu, NU_);
    scan1_kernel<<<sblocks, 1024>>>(cnti, offi, bsumi, NI_);
    scan2_kernel<<<1, 128>>>(bsumu, sblocks);
    scan2_kernel<<<1, 128>>>(bsumi, sblocks);
    scan3_kernel<<<sblocks, 1024>>>(offu, bsumu, curu, NU_);
    scan3_kernel<<<sblocks, 1024>>>(offi, bsumi, curi, NI_);
    fill_kernel<<<(NE_ + 255) / 256, 256>>>(eui, eiu);

    // weight transposes (once)
    transpose_w_kernel<<<(128 * 96  + 255) / 256, 256>>>(Wp_u, Wp_u, wt_pu, 96, 96, 128);
    transpose_w_kernel<<<(128 * 160 + 255) / 256, 256>>>(Wp_i, Wp_i, wt_pi, 160, 160, 128);
    transpose_w_kernel<<<(128 * 256 + 255) / 256, 256>>>(Wl0_ui, Wr0_ui, wt0_ui, 128, 256, 128);
    transpose_w_kernel<<<(128 * 256 + 255) / 256, 256>>>(Wl0_iu, Wr0_iu, wt0_iu, 128, 256, 128);
    transpose_w_kernel<<<(64 * 256 + 255) / 256, 256>>>(Wl1_iu, Wr1_iu, wt1_iu, 128, 256, 64);
    transpose_w_kernel<<<(64 * 256 + 255) / 256, 256>>>(Wl1_ui, Wr1_ui, wt1_ui, 128, 256, 64);

    // projections + relu
    gemm_mma_kernel<FU_, FU_, HH, false, true><<<gblocks, 256, SM_N128>>>(
        x_user, x_user, wt_pu, bp_u, bp_u, bp_u, hu, NU_);
    gemm_mma_kernel<FI_, FI_, HH, false, true><<<gblocks, 256, SM_N128>>>(
        x_item, x_item, wt_pi, bp_i, bp_i, bp_i, hi, NI_);

    // layer 0 aggregation (mean folded in)
    gather_kernel<<<wblocks, 256>>>(hu, eix_ui, offi, cnti, aggi, NI_);
    gather_kernel<<<wblocks, 256>>>(hi, eix_iu, offu, cntu, aggu, NU_);

    // layer 0 SAGE + LN + relu
    gemm_mma_kernel<2 * HH, HH, HH, true, true><<<gblocks, 256, SM_N128>>>(
        aggi, hi, wt0_ui, bl0_ui, g0_i, b0_i, hi1, NI_);
    gemm_mma_kernel<2 * HH, HH, HH, true, true><<<gblocks, 256, SM_N128>>>(
        aggu, hu, wt0_iu, bl0_iu, g0_u, b0_u, hu1, NU_);

    // layer 1 aggregation
    gather_kernel<<<wblocks, 256>>>(hu1, eix_ui, offi, cnti, aggi, NI_);
    gather_kernel<<<wblocks, 256>>>(hi1, eix_iu, offu, cntu, aggu, NU_);

    // layer 1 SAGE + LN (no relu); outputs: [h_u2 | h_i2]
    gemm_mma_kernel<2 * HH, HH, OUTD, true, false><<<gblocks, 256, SM_N64>>>(
        aggu, hu1, wt1_iu, bl1_iu, g1_u, b1_u, out, NU_);
    gemm_mma_kernel<2 * HH, HH, OUTD, true, false><<<gblocks, 256, SM_N64>>>(
        aggi, hi1, wt1_ui, bl1_ui, g1_i, b1_i, out + (size_t)NU_ * OUTD, NI_);
}